// round 2
// baseline (speedup 1.0000x reference)
#include <cuda_runtime.h>
#include <math.h>

#define NEG_INF (-1e30f)

// Problem constants
#define Bn 8
#define Tn 128
#define Dn 512
#define Hn 512
#define Vn 64
#define Un 32
#define Cn 65   // V + 1

// Scratch (allocation-free rules: __device__ globals)
__device__ float g_proj[Bn * Tn * Hn];                 // 2 MB
__device__ float g_den[Bn * Tn * Cn * Cn];             // [b][t][c][k]; k=0 blank raw, k>=1 exp(lex), ~17.3 MB

// ---------------------------------------------------------------------------
// Kernel 1: proj = frames @ W_frame   (M=1024, N=512, K=512)
// BM=BN=64, BK=16, 256 threads, 4x4 micro-tile
// ---------------------------------------------------------------------------
__global__ __launch_bounds__(256) void k_proj(const float* __restrict__ A,
                                              const float* __restrict__ Bm) {
    __shared__ float As[16][64];
    __shared__ float Bs[16][64];

    const int tx = threadIdx.x & 15;
    const int ty = threadIdx.x >> 4;
    const int tid = threadIdx.x;
    const int bm = blockIdx.y * 64;
    const int bn = blockIdx.x * 64;

    float acc[4][4];
#pragma unroll
    for (int i = 0; i < 4; i++)
#pragma unroll
        for (int j = 0; j < 4; j++) acc[i][j] = 0.f;

    for (int kc = 0; kc < Dn; kc += 16) {
#pragma unroll
        for (int l = 0; l < 4; l++) {
            int e = tid + l * 256;
            int k = e & 15, m = e >> 4;
            As[k][m] = A[(size_t)(bm + m) * Dn + kc + k];
        }
#pragma unroll
        for (int l = 0; l < 4; l++) {
            int e = tid + l * 256;
            int n = e & 63, k = e >> 6;
            Bs[k][n] = Bm[(size_t)(kc + k) * Hn + bn + n];
        }
        __syncthreads();
#pragma unroll
        for (int kk = 0; kk < 16; kk++) {
            float4 av = *reinterpret_cast<const float4*>(&As[kk][ty * 4]);
            float4 bv = *reinterpret_cast<const float4*>(&Bs[kk][tx * 4]);
            float a[4] = {av.x, av.y, av.z, av.w};
            float b[4] = {bv.x, bv.y, bv.z, bv.w};
#pragma unroll
            for (int i = 0; i < 4; i++)
#pragma unroll
                for (int j = 0; j < 4; j++) acc[i][j] += a[i] * b[j];
        }
        __syncthreads();
    }

#pragma unroll
    for (int i = 0; i < 4; i++)
#pragma unroll
        for (int j = 0; j < 4; j++)
            g_proj[(size_t)(bm + ty * 4 + i) * Hn + bn + tx * 4 + j] = acc[i][j];
}

// ---------------------------------------------------------------------------
// Kernel 2: per-(b,t) 65x65 logits tile, fused tanh + epilogue exp
//   logits[c][k] = sum_h tanh(proj[bt][h] + ce[c][h]) * Wout[h][k]
//   store k=0 raw (blank), k>=1 exp() (lex)
// 256 threads (16x16), 5x5 micro-tile over padded 80x80.
// ---------------------------------------------------------------------------
__global__ __launch_bounds__(256) void k_logits(const float* __restrict__ ce,
                                                const float* __restrict__ Wout) {
    const int bt = blockIdx.x;          // 0..1023
    __shared__ float p[Hn];             // proj row
    __shared__ float Jt[80 * 65];       // [c][kk], row stride 65 (kk<64 used)
    __shared__ float Wt[64 * 80];       // [kk][ko], ko padded to 80

    const int tid = threadIdx.x;
    const int tx = tid & 15;
    const int ty = tid >> 4;

    for (int i = tid; i < Hn; i += 256) p[i] = g_proj[(size_t)bt * Hn + i];
    // zero padding rows c = 65..79 of Jt (written once, never overwritten)
    for (int i = tid; i < 15 * 65; i += 256) Jt[65 * 65 + i] = 0.f;
    __syncthreads();

    float acc[5][5];
#pragma unroll
    for (int i = 0; i < 5; i++)
#pragma unroll
        for (int j = 0; j < 5; j++) acc[i][j] = 0.f;

    for (int kc = 0; kc < Hn; kc += 64) {
        // fill Jt: 65 x 64 tanh values
        for (int e = tid; e < 65 * 64; e += 256) {
            int c = e >> 6, kk = e & 63;
            Jt[c * 65 + kk] = tanhf(p[kc + kk] + ce[(size_t)c * Hn + kc + kk]);
        }
        // fill Wt: 64 x 80 (pad ko>=65 with 0)
        for (int e = tid; e < 64 * 80; e += 256) {
            int kk = e / 80, ko = e % 80;
            Wt[e] = (ko < Cn) ? Wout[(size_t)(kc + kk) * Cn + ko] : 0.f;
        }
        __syncthreads();
#pragma unroll 8
        for (int kk = 0; kk < 64; kk++) {
            float a[5], b[5];
#pragma unroll
            for (int i = 0; i < 5; i++) a[i] = Jt[(ty + 16 * i) * 65 + kk];
#pragma unroll
            for (int j = 0; j < 5; j++) b[j] = Wt[kk * 80 + tx + 16 * j];
#pragma unroll
            for (int i = 0; i < 5; i++)
#pragma unroll
                for (int j = 0; j < 5; j++) acc[i][j] += a[i] * b[j];
        }
        __syncthreads();
    }

    float* outp = g_den + (size_t)bt * (Cn * Cn);
#pragma unroll
    for (int i = 0; i < 5; i++) {
        int c = ty + 16 * i;
        if (c >= Cn) continue;
#pragma unroll
        for (int j = 0; j < 5; j++) {
            int k = tx + 16 * j;
            if (k >= Cn) continue;
            float v = acc[i][j];
            outp[c * Cn + k] = (k == 0) ? v : expf(v);
        }
    }
}

// ---------------------------------------------------------------------------
// Kernel 3: the two scans, one block per batch.
// tid 0..63  : denominator state v+1  (matvec over pre-exponentiated lex)
// tid 127    : denominator state 0 (stay only)
// tid 64..96 : numerator states j = tid-64 (0..32)
// Tile (65*65 floats) double-buffered with register prefetch of t+1.
// ---------------------------------------------------------------------------
__device__ __forceinline__ float log_add_exp(float a, float b) {
    float m = fmaxf(a, b);
    float d = fminf(a, b) - m;
    return m + log1pf(expf(d));
}

__global__ __launch_bounds__(128) void k_scan(const int* __restrict__ num_frames,
                                              const int* __restrict__ labels,
                                              const int* __restrict__ num_labels,
                                              float* __restrict__ out) {
    const int b = blockIdx.x;
    const int tid = threadIdx.x;
    const int Tb = num_frames[b];

    __shared__ float alpha[Cn];       // denominator alpha
    __shared__ float anum[Un + 1];    // numerator alpha
    __shared__ float ea[Cn];          // exp(alpha - amax)
    __shared__ int ctx[Un + 1];       // ctx[0]=0, ctx[j]=labels[b][j-1]
    __shared__ float tile[2][Cn * Cn];

    if (tid < Un + 1) {
        ctx[tid] = (tid == 0) ? 0 : labels[b * Un + tid - 1];
        anum[tid] = (tid == 0) ? 0.f : NEG_INF;
    }
    if (tid < Cn) alpha[tid] = (tid == 0) ? 0.f : NEG_INF;

    const float* base = g_den + (size_t)b * Tn * (Cn * Cn);
    // load tile 0
#pragma unroll
    for (int k = 0; k < 34; k++) {
        int i = tid + k * 128;
        if (i < Cn * Cn) tile[0][i] = base[i];
    }
    __syncthreads();

    for (int t = 0; t < Tb; t++) {
        const int cur = t & 1;
        const float* Tt = tile[cur];

        // issue prefetch of tile t+1 into registers (overlaps compute)
        float pre[34];
        const bool do_pre = (t + 1 < Tb);
        const float* bnext = base + (size_t)(t + 1) * (Cn * Cn);
#pragma unroll
        for (int k = 0; k < 34; k++) {
            int i = tid + k * 128;
            if (do_pre && i < Cn * Cn) pre[k] = bnext[i];
        }

        // amax over alpha (redundant per-thread, cheap)
        float m0 = NEG_INF, m1 = NEG_INF;
#pragma unroll 4
        for (int c = 0; c < 64; c += 2) {
            m0 = fmaxf(m0, alpha[c]);
            m1 = fmaxf(m1, alpha[c + 1]);
        }
        float amax = fmaxf(fmaxf(m0, m1), alpha[64]);

        if (tid < Cn) ea[tid] = expf(alpha[tid] - amax);
        __syncthreads();

        float nv = 0.f;      // new denominator value for this thread's state
        float nnum = 0.f;    // new numerator value

        if (tid < 64) {
            const int v = tid;
            float s0 = 0.f, s1 = 0.f, s2 = 0.f, s3 = 0.f;
#pragma unroll 8
            for (int c = 0; c < 64; c += 4) {
                s0 += ea[c]     * Tt[c * Cn + v + 1];
                s1 += ea[c + 1] * Tt[(c + 1) * Cn + v + 1];
                s2 += ea[c + 2] * Tt[(c + 2) * Cn + v + 1];
                s3 += ea[c + 3] * Tt[(c + 3) * Cn + v + 1];
            }
            float s = (s0 + s1) + (s2 + s3) + ea[64] * Tt[64 * Cn + v + 1];
            float mv = amax + logf(s);
            float stay = alpha[v + 1] + Tt[(v + 1) * Cn];   // blank at k=0
            nv = log_add_exp(stay, mv);
        } else if (tid == 127) {
            nv = alpha[0] + Tt[0];                          // new alpha[0] = stay[0]
        } else if (tid < 64 + Un + 1) {
            const int j = tid - 64;
            float a1 = anum[j] + Tt[ctx[j] * Cn];           // blank at context
            float sh = NEG_INF;
            if (j > 0) {
                // lex_num[j-1] = log(E[ctx[j-1]][labels[j-1]]) ; labels[j-1] == ctx[j]
                sh = anum[j - 1] + logf(Tt[ctx[j - 1] * Cn + ctx[j]]);
            }
            nnum = log_add_exp(a1, sh);
        }
        __syncthreads();

        if (tid < 64) alpha[tid + 1] = nv;
        else if (tid == 127) alpha[0] = nv;
        else if (tid < 64 + Un + 1) anum[tid - 64] = nnum;

        // commit prefetch into the other buffer
#pragma unroll
        for (int k = 0; k < 34; k++) {
            int i = tid + k * 128;
            if (do_pre && i < Cn * Cn) tile[1 - cur][i] = pre[k];
        }
        __syncthreads();
    }

    if (tid == 0) {
        float m = NEG_INF;
        for (int c = 0; c < Cn; c++) m = fmaxf(m, alpha[c]);
        float s = 0.f;
        for (int c = 0; c < Cn; c++) s += expf(alpha[c] - m);
        float den = m + logf(s);
        float num = anum[num_labels[b]];
        out[b] = den - num;
    }
}

// ---------------------------------------------------------------------------
extern "C" void kernel_launch(void* const* d_in, const int* in_sizes, int n_in,
                              void* d_out, int out_size) {
    const float* frames = (const float*)d_in[0];   // (8,128,512)
    const float* Wf     = (const float*)d_in[1];   // (512,512)
    const float* ce     = (const float*)d_in[2];   // (65,512)
    const float* Wo     = (const float*)d_in[3];   // (512,65)
    const int* nf       = (const int*)d_in[4];     // (8,)
    const int* labels   = (const int*)d_in[5];     // (8,32)
    const int* nl       = (const int*)d_in[6];     // (8,)
    float* out = (float*)d_out;                    // (8,)

    k_proj<<<dim3(Hn / 64, (Bn * Tn) / 64), 256>>>(frames, Wf);
    k_logits<<<Bn * Tn, 256>>>(ce, Wo);
    k_scan<<<Bn, 128>>>(nf, labels, nl, out);
}

// round 5
// speedup vs baseline: 1.5538x; 1.5538x over previous
#include <cuda_runtime.h>
#include <cuda_bf16.h>
#include <math.h>
#include <stdint.h>

#define NEG_INF (-1e30f)

// Problem constants
#define Bn 8
#define Tn 128
#define Dn 512
#define Hn 512
#define Vn 64
#define Un 32
#define Cn 65          // V + 1
#define CSTRIDE 66     // padded row stride of transposed tile (even -> float2)
#define TILE_F (Cn * CSTRIDE)       // 4290 floats per (b,t)
#define MROWS (Bn * Tn * Cn)        // 66560 = 520 * 128
#define NB_LOGITS (MROWS / 128)     // 520

// SMEM tile geometry for k_logits (strides in bf16 elements)
#define ASTRIDE 520                 // 128 rows  x 512 k  (pad 8 -> conflict-free frags)
#define BSTRIDE 520                 // 72  rows  x 512 k
#define A_ELEMS (128 * ASTRIDE)     // 66560 bf16 = 133120 B
#define B_ELEMS (72 * BSTRIDE)      //  37440 bf16 =  74880 B
#define DYN_SMEM ((A_ELEMS + B_ELEMS) * 2)   // 208000 B
#define DSTRIDE 132                 // fp32 stage stride (conflict-free)

// Scratch (__device__ globals; no allocation allowed). Explicit 16B alignment:
// these are vector-cast (float4/uint4/float2) and the language only guarantees
// element alignment.
__device__ __align__(16) float g_proj[Bn * Tn * Hn];          // 2 MB
__device__ __align__(16) float g_den[Bn * Tn * TILE_F];       // transposed: [bt][k*66 + c]
__device__ __align__(16) __nv_bfloat16 g_WoutT[72 * 512];     // WoutT[n][k] = Wout[k][n], bf16

// ---------------------------------------------------------------------------
__device__ __forceinline__ float tanh_fast(float x) {
    float y; asm("tanh.approx.f32 %0, %1;" : "=f"(y) : "f"(x)); return y;
}

__device__ __forceinline__ void mma16816(float* c, const uint32_t* a, const uint32_t* b) {
    asm volatile(
        "mma.sync.aligned.m16n8k16.row.col.f32.bf16.bf16.f32 "
        "{%0,%1,%2,%3}, {%4,%5,%6,%7}, {%8,%9}, {%0,%1,%2,%3};"
        : "+f"(c[0]), "+f"(c[1]), "+f"(c[2]), "+f"(c[3])
        : "r"(a[0]), "r"(a[1]), "r"(a[2]), "r"(a[3]), "r"(b[0]), "r"(b[1]));
}

// ---------------------------------------------------------------------------
// Kernel 0: transpose + bf16-convert Wout -> g_WoutT[n][k]  (rows n>=65 zero)
// ---------------------------------------------------------------------------
__global__ void k_prep(const float* __restrict__ Wo) {
    const int tid = threadIdx.x + blockIdx.x * blockDim.x;
    for (int e = tid; e < 72 * 512; e += blockDim.x * gridDim.x) {
        int n = e >> 9;
        int k = e & 511;
        float v = (n < Cn) ? Wo[k * Cn + n] : 0.f;
        g_WoutT[e] = __float2bfloat16(v);
    }
}

// ---------------------------------------------------------------------------
// Kernel 1: proj = frames @ W_frame  (M=1024, N=512, K=512)
// BM=64, BN=32, BK=32, 128 threads, 4x4 micro -> 256 blocks
// ---------------------------------------------------------------------------
__global__ __launch_bounds__(128) void k_proj(const float* __restrict__ A,
                                              const float* __restrict__ Bm) {
    __shared__ __align__(16) float As[32][68];   // [k][m]
    __shared__ __align__(16) float Bs[32][40];   // [k][n]

    const int tid = threadIdx.x;
    const int tx = tid & 7;        // 0..7  -> n*4
    const int ty = tid >> 3;       // 0..15 -> m*4
    const int bm = blockIdx.y * 64;
    const int bn = blockIdx.x * 32;

    float acc[4][4];
#pragma unroll
    for (int i = 0; i < 4; i++)
#pragma unroll
        for (int j = 0; j < 4; j++) acc[i][j] = 0.f;

    for (int kc = 0; kc < Dn; kc += 32) {
#pragma unroll
        for (int l = 0; l < 4; l++) {
            int idx = tid + l * 128;
            int m = idx >> 3, kq = idx & 7;
            float4 v = *reinterpret_cast<const float4*>(&A[(size_t)(bm + m) * Dn + kc + kq * 4]);
            As[kq * 4 + 0][m] = v.x;
            As[kq * 4 + 1][m] = v.y;
            As[kq * 4 + 2][m] = v.z;
            As[kq * 4 + 3][m] = v.w;
        }
#pragma unroll
        for (int l = 0; l < 2; l++) {
            int idx = tid + l * 128;
            int kb = idx >> 3, n4 = idx & 7;
            *reinterpret_cast<float4*>(&Bs[kb][n4 * 4]) =
                *reinterpret_cast<const float4*>(&Bm[(size_t)(kc + kb) * Hn + bn + n4 * 4]);
        }
        __syncthreads();
#pragma unroll
        for (int kk = 0; kk < 32; kk++) {
            float4 av = *reinterpret_cast<const float4*>(&As[kk][ty * 4]);
            float4 bv = *reinterpret_cast<const float4*>(&Bs[kk][tx * 4]);
            float a[4] = {av.x, av.y, av.z, av.w};
            float b[4] = {bv.x, bv.y, bv.z, bv.w};
#pragma unroll
            for (int i = 0; i < 4; i++)
#pragma unroll
                for (int j = 0; j < 4; j++) acc[i][j] += a[i] * b[j];
        }
        __syncthreads();
    }

#pragma unroll
    for (int i = 0; i < 4; i++) {
        float4 v = make_float4(acc[i][0], acc[i][1], acc[i][2], acc[i][3]);
        *reinterpret_cast<float4*>(&g_proj[(size_t)(bm + ty * 4 + i) * Hn + bn + tx * 4]) = v;
    }
}

// ---------------------------------------------------------------------------
// Kernel 2: logits via mma.sync bf16 (m16n8k16).
// Block = 128 flattened (bt,c) rows, N=72 (65 valid), K=512 fully in SMEM.
// 128 threads = 4 warps, each warp: 32 rows (2 m-tiles) x 9 n-tiles.
// A = tanh(proj[bt] + ce[c]) computed into SMEM as bf16.
// Epilogue stages D in SMEM, stores transposed g_den[bt][k*66+c]
// (k=0 raw blank; k>=1 exp(lex)).
// ---------------------------------------------------------------------------
__global__ __launch_bounds__(128) void k_logits(const float* __restrict__ ce) {
    extern __shared__ __align__(16) __nv_bfloat16 dynsmem[];
    __nv_bfloat16* Asm = dynsmem;              // [128][ASTRIDE]
    __nv_bfloat16* Bsm = dynsmem + A_ELEMS;    // [72][BSTRIDE]
    __shared__ __align__(16) float p[3 * 512];

    const int tid = threadIdx.x;
    const int wid = tid >> 5;
    const int lane = tid & 31;
    const int gq = lane >> 2;     // groupID 0..7
    const int tg = lane & 3;      // thread-in-group
    const int g0 = blockIdx.x * 128;
    const int bt0 = g0 / 65;

    // proj rows this block touches (<=3 bts)
    for (int i = tid; i < 3 * 512; i += 128) {
        int bt = bt0 + (i >> 9);
        p[i] = (bt < Bn * Tn) ? g_proj[(size_t)bt * Hn + (i & 511)] : 0.f;
    }
    // copy pre-transposed bf16 B tile (src stride 512 -> dst stride 520)
    for (int e = tid; e < 72 * 64; e += 128) {
        int n = e >> 6, kq = e & 63;
        *reinterpret_cast<uint4*>(&Bsm[n * BSTRIDE + kq * 8]) =
            *reinterpret_cast<const uint4*>(&g_WoutT[n * 512 + kq * 8]);
    }
    __syncthreads();

    // A tile: tanh(p + ce), 2 elems/iter
    for (int e = tid; e < 128 * 256; e += 128) {
        int r = e >> 8;
        int h2 = (e & 255) << 1;
        int g = g0 + r;
        int bt = g / 65;
        int c = g - bt * 65;
        float2 pe = *reinterpret_cast<const float2*>(&p[(bt - bt0) * 512 + h2]);
        float2 cv = *reinterpret_cast<const float2*>(&ce[(size_t)c * Hn + h2]);
        __nv_bfloat162 bb = __floats2bfloat162_rn(tanh_fast(pe.x + cv.x),
                                                  tanh_fast(pe.y + cv.y));
        *reinterpret_cast<uint32_t*>(&Asm[r * ASTRIDE + h2]) =
            *reinterpret_cast<uint32_t*>(&bb);
    }
    __syncthreads();

    // Main loop
    float acc[2][9][4];
#pragma unroll
    for (int mt = 0; mt < 2; mt++)
#pragma unroll
        for (int nt = 0; nt < 9; nt++)
#pragma unroll
            for (int i = 0; i < 4; i++) acc[mt][nt][i] = 0.f;

    const int wbase = wid * 32;
#pragma unroll 2
    for (int kk = 0; kk < 32; kk++) {
        const int k0 = kk * 16;
        uint32_t bf[9][2];
#pragma unroll
        for (int nt = 0; nt < 9; nt++) {
            int n = nt * 8 + gq;
            bf[nt][0] = *reinterpret_cast<const uint32_t*>(&Bsm[n * BSTRIDE + k0 + tg * 2]);
            bf[nt][1] = *reinterpret_cast<const uint32_t*>(&Bsm[n * BSTRIDE + k0 + 8 + tg * 2]);
        }
#pragma unroll
        for (int mt = 0; mt < 2; mt++) {
            const int r0 = wbase + mt * 16 + gq;
            uint32_t af[4];
            af[0] = *reinterpret_cast<const uint32_t*>(&Asm[r0 * ASTRIDE + k0 + tg * 2]);
            af[1] = *reinterpret_cast<const uint32_t*>(&Asm[(r0 + 8) * ASTRIDE + k0 + tg * 2]);
            af[2] = *reinterpret_cast<const uint32_t*>(&Asm[r0 * ASTRIDE + k0 + 8 + tg * 2]);
            af[3] = *reinterpret_cast<const uint32_t*>(&Asm[(r0 + 8) * ASTRIDE + k0 + 8 + tg * 2]);
#pragma unroll
            for (int nt = 0; nt < 9; nt++) mma16816(acc[mt][nt], af, bf[nt]);
        }
    }
    __syncthreads();   // done reading Asm/Bsm; reuse as stage

    // Stage D into SMEM: d_sm[col][row], stride DSTRIDE (conflict-free)
    float* d_sm = reinterpret_cast<float*>(dynsmem);   // 72*132 floats = 38016 B
#pragma unroll
    for (int mt = 0; mt < 2; mt++) {
        const int r0 = wbase + mt * 16 + gq;
#pragma unroll
        for (int nt = 0; nt < 9; nt++) {
            const int col = nt * 8 + tg * 2;
            d_sm[col * DSTRIDE + r0]           = acc[mt][nt][0];
            d_sm[(col + 1) * DSTRIDE + r0]     = acc[mt][nt][1];
            d_sm[col * DSTRIDE + r0 + 8]       = acc[mt][nt][2];
            d_sm[(col + 1) * DSTRIDE + r0 + 8] = acc[mt][nt][3];
        }
    }
    __syncthreads();

    // Drain: coalesced transposed stores (k=0 raw, k>=1 exp)
    for (int e = tid; e < Cn * 128; e += 128) {
        int k = e >> 7;
        int r = e & 127;
        int g = g0 + r;
        int bt = g / 65;
        int c = g - bt * 65;
        float v = d_sm[k * DSTRIDE + r];
        g_den[(size_t)bt * TILE_F + k * CSTRIDE + c] = (k == 0) ? v : __expf(v);
    }
}

// ---------------------------------------------------------------------------
// Kernel 3: scans. One block per batch, 128 threads.
//  tid 0..63  : denominator state v+1 (matvec over exp(lex), transposed tile)
//  tid 127    : denominator state 0
//  tid 64..96 : numerator state j = tid-64 (anum double-buffered)
// Transposed tile: Tt[k*66 + c]; blank row k=0. 2 barriers/step.
// ---------------------------------------------------------------------------
__device__ __forceinline__ float log_add_exp(float a, float b) {
    float m = fmaxf(a, b);
    float d = fminf(a, b) - m;
    return m + log1pf(__expf(d));
}

__global__ __launch_bounds__(128) void k_scan(const int* __restrict__ num_frames,
                                              const int* __restrict__ labels,
                                              const int* __restrict__ num_labels,
                                              float* __restrict__ out) {
    const int b = blockIdx.x;
    const int tid = threadIdx.x;
    const int Tb = num_frames[b];

    __shared__ __align__(16) float ea[66];
    __shared__ float anum[2][Un + 1];
    __shared__ int ctx[Un + 1];
    __shared__ float maxw[4];
    __shared__ __align__(16) float tile[2][TILE_F];
    __shared__ float afin[Cn];

    if (tid < Un + 1) {
        ctx[tid] = (tid == 0) ? 0 : labels[b * Un + tid - 1];
        anum[0][tid] = (tid == 0) ? 0.f : NEG_INF;
    }

    const bool den_lo = (tid < 64);
    const bool den_hi = (tid == 127);
    float av = den_hi ? 0.f : NEG_INF;   // reg-resident alpha (state tid+1 / state 0)

    const float* base = g_den + (size_t)(b * Tn) * TILE_F;
#pragma unroll
    for (int k = 0; k < 34; k++) {
        int i = tid + k * 128;
        if (i < TILE_F) tile[0][i] = base[i];
    }
    __syncthreads();

    for (int t = 0; t < Tb; t++) {
        const int cur = t & 1;
        const float* Tt = tile[cur];
        const bool do_pre = (t + 1 < Tb);
        const float* bnx = base + (size_t)(t + 1) * TILE_F;
        float pre[34];
#pragma unroll
        for (int k = 0; k < 34; k++) {
            int i = tid + k * 128;
            if (do_pre && i < TILE_F) pre[k] = bnx[i];
        }

        // amax via warp shuffles (warps 0,1; tid 127 alone)
        if (den_lo) {
            float m = av;
#pragma unroll
            for (int o = 16; o; o >>= 1) m = fmaxf(m, __shfl_xor_sync(0xffffffffu, m, o));
            if ((tid & 31) == 0) maxw[tid >> 5] = m;
        }
        if (den_hi) maxw[3] = av;
        __syncthreads();

        const float amax = fmaxf(fmaxf(maxw[0], maxw[1]), maxw[3]);
        if (den_lo) ea[tid + 1] = __expf(av - amax);
        if (den_hi) ea[0] = __expf(av - amax);
        __syncthreads();

        if (den_lo) {
            const int v = tid;
            const float* rp = Tt + (v + 1) * CSTRIDE;
            const float2* r2 = reinterpret_cast<const float2*>(rp);
            const float2* e2 = reinterpret_cast<const float2*>(ea);
            float s0 = 0.f, s1 = 0.f, s2 = 0.f, s3 = 0.f;
#pragma unroll 8
            for (int c2 = 0; c2 < 32; c2 += 2) {
                float2 a0 = r2[c2],     b0 = e2[c2];
                float2 a1 = r2[c2 + 1], b1 = e2[c2 + 1];
                s0 += a0.x * b0.x; s1 += a0.y * b0.y;
                s2 += a1.x * b1.x; s3 += a1.y * b1.y;
            }
            float s = (s0 + s1) + (s2 + s3) + rp[64] * ea[64];
            float mv = amax + __logf(s);
            float stay = av + Tt[v + 1];       // blank for context v+1 (row 0)
            av = log_add_exp(stay, mv);
        } else if (den_hi) {
            av += Tt[0];                        // state 0: stay only
        } else if (tid <= 64 + Un) {
            const int j = tid - 64;
            const int pp = cur;
            float a1 = anum[pp][j] + Tt[ctx[j]];               // blank at context
            float nn;
            if (j > 0) {
                float sh = anum[pp][j - 1] + __logf(Tt[ctx[j] * CSTRIDE + ctx[j - 1]]);
                nn = log_add_exp(a1, sh);
            } else {
                nn = a1;
            }
            anum[1 - pp][j] = nn;
        }

        // commit prefetch into the other buffer
#pragma unroll
        for (int k = 0; k < 34; k++) {
            int i = tid + k * 128;
            if (do_pre && i < TILE_F) tile[1 - cur][i] = pre[k];
        }
    }

    __syncthreads();
    if (den_lo) afin[tid + 1] = av;
    if (den_hi) afin[0] = av;
    __syncthreads();

    if (tid == 0) {
        float m = NEG_INF;
        for (int c = 0; c < Cn; c++) m = fmaxf(m, afin[c]);
        float s = 0.f;
        for (int c = 0; c < Cn; c++) s += __expf(afin[c] - m);
        float den = m + __logf(s);
        float num = anum[Tb & 1][num_labels[b]];
        out[b] = den - num;
    }
}

// ---------------------------------------------------------------------------
extern "C" void kernel_launch(void* const* d_in, const int* in_sizes, int n_in,
                              void* d_out, int out_size) {
    const float* frames = (const float*)d_in[0];   // (8,128,512)
    const float* Wf     = (const float*)d_in[1];   // (512,512)
    const float* ce     = (const float*)d_in[2];   // (65,512)
    const float* Wo     = (const float*)d_in[3];   // (512,65)
    const int* nf       = (const int*)d_in[4];     // (8,)
    const int* labels   = (const int*)d_in[5];     // (8,32)
    const int* nl       = (const int*)d_in[6];     // (8,)
    float* out = (float*)d_out;                    // (8,)

    // Not a stream op; safe under graph capture, and no static guards allowed.
    cudaFuncSetAttribute(k_logits, cudaFuncAttributeMaxDynamicSharedMemorySize, DYN_SMEM);

    k_prep<<<4, 256>>>(Wo);
    k_proj<<<dim3(Hn / 32, (Bn * Tn) / 64), 128>>>(frames, Wf);
    k_logits<<<NB_LOGITS, 128, DYN_SMEM>>>(ce);
    k_scan<<<Bn, 128>>>(nf, labels, nl, out);
}

// round 6
// speedup vs baseline: 2.0549x; 1.3225x over previous
#include <cuda_runtime.h>
#include <cuda_bf16.h>
#include <math.h>
#include <stdint.h>

#define NEG_INF (-1e30f)

// Problem constants
#define Bn 8
#define Tn 128
#define Dn 512
#define Hn 512
#define Vn 64
#define Un 32
#define Cn 65          // V + 1
#define CSTRIDE 67     // odd row stride -> conflict-free scalar LDS in scan
#define TILE_PAD 4480  // 35*128 floats per (b,t) tile (>= 65*67=4355), 16B-mult
#define TILE_BYTES (TILE_PAD * 4)   // 17920
#define MROWS (Bn * Tn * Cn)        // 66560 = 520 * 128
#define NB_LOGITS (MROWS / 128)     // 520

// SMEM tile geometry for k_logits (strides in bf16 elements)
#define ASTRIDE 520                 // 128 rows  x 512 k  (pad 8 -> conflict-free frags)
#define BSTRIDE 520                 // 72  rows  x 512 k
#define A_ELEMS (128 * ASTRIDE)     // 133120 B
#define B_ELEMS (72 * BSTRIDE)      //  74880 B
#define DYN_SMEM ((A_ELEMS + B_ELEMS) * 2)   // 208000 B
#define DSTRIDE 132                 // fp32 stage stride (conflict-free)

#define SCAN_SMEM (4 * TILE_BYTES)  // 71680 B, 4-deep cp.async ring

// Scratch (__device__ globals; no allocation allowed), 16B-aligned for vector casts.
__device__ __align__(16) float g_proj[Bn * Tn * Hn];             // 2 MB
__device__ __align__(16) float g_den[Bn * Tn * TILE_PAD];        // [bt][k*67 + c] = exp(logit), ~18.4 MB
__device__ __align__(16) __nv_bfloat16 g_WoutT[72 * 512];        // WoutT[n][k] = Wout[k][n], bf16

// ---------------------------------------------------------------------------
__device__ __forceinline__ float tanh_fast(float x) {
    float y; asm("tanh.approx.f32 %0, %1;" : "=f"(y) : "f"(x)); return y;
}
__device__ __forceinline__ uint32_t smem_u32(const void* p) {
    uint32_t a;
    asm("{ .reg .u64 t; cvta.to.shared.u64 t, %1; cvt.u32.u64 %0, t; }" : "=r"(a) : "l"(p));
    return a;
}
__device__ __forceinline__ void cp_async16(uint32_t saddr, const void* g) {
    asm volatile("cp.async.cg.shared.global [%0], [%1], 16;" :: "r"(saddr), "l"(g));
}
#define CP_COMMIT() asm volatile("cp.async.commit_group;" ::: "memory")
#define CP_WAIT2()  asm volatile("cp.async.wait_group 2;" ::: "memory")

__device__ __forceinline__ void mma16816(float* c, const uint32_t* a, const uint32_t* b) {
    asm volatile(
        "mma.sync.aligned.m16n8k16.row.col.f32.bf16.bf16.f32 "
        "{%0,%1,%2,%3}, {%4,%5,%6,%7}, {%8,%9}, {%0,%1,%2,%3};"
        : "+f"(c[0]), "+f"(c[1]), "+f"(c[2]), "+f"(c[3])
        : "r"(a[0]), "r"(a[1]), "r"(a[2]), "r"(a[3]), "r"(b[0]), "r"(b[1]));
}

// ---------------------------------------------------------------------------
// Kernel 0: transpose + bf16-convert Wout -> g_WoutT[n][k]  (rows n>=65 zero)
// ---------------------------------------------------------------------------
__global__ void k_prep(const float* __restrict__ Wo) {
    const int tid = threadIdx.x + blockIdx.x * blockDim.x;
    for (int e = tid; e < 72 * 512; e += blockDim.x * gridDim.x) {
        int n = e >> 9;
        int k = e & 511;
        float v = (n < Cn) ? Wo[k * Cn + n] : 0.f;
        g_WoutT[e] = __float2bfloat16(v);
    }
}

// ---------------------------------------------------------------------------
// Kernel 1: proj = frames @ W_frame  (M=1024, N=512, K=512)
// BM=64, BN=32, BK=32, 128 threads, 4x4 micro -> 256 blocks
// ---------------------------------------------------------------------------
__global__ __launch_bounds__(128) void k_proj(const float* __restrict__ A,
                                              const float* __restrict__ Bm) {
    __shared__ __align__(16) float As[32][68];   // [k][m]
    __shared__ __align__(16) float Bs[32][40];   // [k][n]

    const int tid = threadIdx.x;
    const int tx = tid & 7;        // 0..7  -> n*4
    const int ty = tid >> 3;       // 0..15 -> m*4
    const int bm = blockIdx.y * 64;
    const int bn = blockIdx.x * 32;

    float acc[4][4];
#pragma unroll
    for (int i = 0; i < 4; i++)
#pragma unroll
        for (int j = 0; j < 4; j++) acc[i][j] = 0.f;

    for (int kc = 0; kc < Dn; kc += 32) {
#pragma unroll
        for (int l = 0; l < 4; l++) {
            int idx = tid + l * 128;
            int m = idx >> 3, kq = idx & 7;
            float4 v = *reinterpret_cast<const float4*>(&A[(size_t)(bm + m) * Dn + kc + kq * 4]);
            As[kq * 4 + 0][m] = v.x;
            As[kq * 4 + 1][m] = v.y;
            As[kq * 4 + 2][m] = v.z;
            As[kq * 4 + 3][m] = v.w;
        }
#pragma unroll
        for (int l = 0; l < 2; l++) {
            int idx = tid + l * 128;
            int kb = idx >> 3, n4 = idx & 7;
            *reinterpret_cast<float4*>(&Bs[kb][n4 * 4]) =
                *reinterpret_cast<const float4*>(&Bm[(size_t)(kc + kb) * Hn + bn + n4 * 4]);
        }
        __syncthreads();
#pragma unroll
        for (int kk = 0; kk < 32; kk++) {
            float4 av = *reinterpret_cast<const float4*>(&As[kk][ty * 4]);
            float4 bv = *reinterpret_cast<const float4*>(&Bs[kk][tx * 4]);
            float a[4] = {av.x, av.y, av.z, av.w};
            float b[4] = {bv.x, bv.y, bv.z, bv.w};
#pragma unroll
            for (int i = 0; i < 4; i++)
#pragma unroll
                for (int j = 0; j < 4; j++) acc[i][j] += a[i] * b[j];
        }
        __syncthreads();
    }

#pragma unroll
    for (int i = 0; i < 4; i++) {
        float4 v = make_float4(acc[i][0], acc[i][1], acc[i][2], acc[i][3]);
        *reinterpret_cast<float4*>(&g_proj[(size_t)(bm + ty * 4 + i) * Hn + bn + tx * 4]) = v;
    }
}

// ---------------------------------------------------------------------------
// Kernel 2: logits via mma.sync bf16 (m16n8k16).
// Block = 128 flattened (bt,c) rows, N=72 (65 valid), K=512 fully in SMEM.
// Epilogue stages D in SMEM, stores EXP of all logits transposed into
// g_den[bt][k*67 + c] (k=0 is blank).
// ---------------------------------------------------------------------------
__global__ __launch_bounds__(128) void k_logits(const float* __restrict__ ce) {
    extern __shared__ __align__(16) __nv_bfloat16 dynsmem[];
    __nv_bfloat16* Asm = dynsmem;              // [128][ASTRIDE]
    __nv_bfloat16* Bsm = dynsmem + A_ELEMS;    // [72][BSTRIDE]
    __shared__ __align__(16) float p[3 * 512];

    const int tid = threadIdx.x;
    const int wid = tid >> 5;
    const int lane = tid & 31;
    const int gq = lane >> 2;     // groupID 0..7
    const int tg = lane & 3;      // thread-in-group
    const int g0 = blockIdx.x * 128;
    const int bt0 = g0 / 65;
    const int c00 = g0 - bt0 * 65;

    // proj rows this block touches (<=3 bts)
    for (int i = tid; i < 3 * 512; i += 128) {
        int bt = bt0 + (i >> 9);
        p[i] = (bt < Bn * Tn) ? g_proj[(size_t)bt * Hn + (i & 511)] : 0.f;
    }
    // copy pre-transposed bf16 B tile (src stride 512 -> dst stride 520)
    for (int e = tid; e < 72 * 64; e += 128) {
        int n = e >> 6, kq = e & 63;
        *reinterpret_cast<uint4*>(&Bsm[n * BSTRIDE + kq * 8]) =
            *reinterpret_cast<const uint4*>(&g_WoutT[n * 512 + kq * 8]);
    }
    __syncthreads();

    // A tile: row-walk, division-free. Thread owns cols [tid*4, tid*4+4).
    {
        int bt = bt0, c = c00;
        const int col = tid * 4;
#pragma unroll 4
        for (int r = 0; r < 128; r++) {
            int pb = bt - bt0;
            float4 pe = *reinterpret_cast<const float4*>(&p[pb * 512 + col]);
            float4 cv = *reinterpret_cast<const float4*>(&ce[(size_t)c * Hn + col]);
            __nv_bfloat162 b0 = __floats2bfloat162_rn(tanh_fast(pe.x + cv.x),
                                                      tanh_fast(pe.y + cv.y));
            __nv_bfloat162 b1 = __floats2bfloat162_rn(tanh_fast(pe.z + cv.z),
                                                      tanh_fast(pe.w + cv.w));
            uint2 pk = make_uint2(*reinterpret_cast<uint32_t*>(&b0),
                                  *reinterpret_cast<uint32_t*>(&b1));
            *reinterpret_cast<uint2*>(&Asm[r * ASTRIDE + col]) = pk;
            if (++c == 65) { c = 0; ++bt; }
        }
    }
    __syncthreads();

    // Main loop
    float acc[2][9][4];
#pragma unroll
    for (int mt = 0; mt < 2; mt++)
#pragma unroll
        for (int nt = 0; nt < 9; nt++)
#pragma unroll
            for (int i = 0; i < 4; i++) acc[mt][nt][i] = 0.f;

    const int wbase = wid * 32;
#pragma unroll 2
    for (int kk = 0; kk < 32; kk++) {
        const int k0 = kk * 16;
        uint32_t bf[9][2];
#pragma unroll
        for (int nt = 0; nt < 9; nt++) {
            int n = nt * 8 + gq;
            bf[nt][0] = *reinterpret_cast<const uint32_t*>(&Bsm[n * BSTRIDE + k0 + tg * 2]);
            bf[nt][1] = *reinterpret_cast<const uint32_t*>(&Bsm[n * BSTRIDE + k0 + 8 + tg * 2]);
        }
#pragma unroll
        for (int mt = 0; mt < 2; mt++) {
            const int r0 = wbase + mt * 16 + gq;
            uint32_t af[4];
            af[0] = *reinterpret_cast<const uint32_t*>(&Asm[r0 * ASTRIDE + k0 + tg * 2]);
            af[1] = *reinterpret_cast<const uint32_t*>(&Asm[(r0 + 8) * ASTRIDE + k0 + tg * 2]);
            af[2] = *reinterpret_cast<const uint32_t*>(&Asm[r0 * ASTRIDE + k0 + 8 + tg * 2]);
            af[3] = *reinterpret_cast<const uint32_t*>(&Asm[(r0 + 8) * ASTRIDE + k0 + 8 + tg * 2]);
#pragma unroll
            for (int nt = 0; nt < 9; nt++) mma16816(acc[mt][nt], af, bf[nt]);
        }
    }
    __syncthreads();   // done reading Asm/Bsm; reuse as stage

    // Stage D into SMEM: d_sm[col][row], stride DSTRIDE (conflict-free)
    float* d_sm = reinterpret_cast<float*>(dynsmem);   // 72*132 floats
#pragma unroll
    for (int mt = 0; mt < 2; mt++) {
        const int r0 = wbase + mt * 16 + gq;
#pragma unroll
        for (int nt = 0; nt < 9; nt++) {
            const int col = nt * 8 + tg * 2;
            d_sm[col * DSTRIDE + r0]           = acc[mt][nt][0];
            d_sm[(col + 1) * DSTRIDE + r0]     = acc[mt][nt][1];
            d_sm[col * DSTRIDE + r0 + 8]       = acc[mt][nt][2];
            d_sm[(col + 1) * DSTRIDE + r0 + 8] = acc[mt][nt][3];
        }
    }
    __syncthreads();

    // Drain: thread owns row r=tid -> fixed (bt,c). exp() of every logit.
    {
        const int g = g0 + tid;
        const int bt = g / 65;            // once per thread
        const int c = g - bt * 65;
        float* outp = g_den + (size_t)bt * TILE_PAD + c;
#pragma unroll
        for (int k = 0; k < Cn; k++)
            outp[k * CSTRIDE] = __expf(d_sm[k * DSTRIDE + tid]);
    }
}

// ---------------------------------------------------------------------------
// Kernel 3: scans, one block/batch, 128 threads.
// Denominator in LINEAR domain: beta = exp(alpha - offset).
//   beta_new[v+1] = beta[v+1]*Ebl[v+1] + sum_c beta[c]*E[c][v+1]   (tid 0..63)
//   beta_new[0]   = beta[0]*Ebl[0]                                  (tid 127)
// Power-of-2 renorm every 4 steps (exact); offset tracked as integer exponent.
// Numerator (tid 64..96) stays in log domain (reads log via __logf of tile).
// Tiles streamed by cp.async, 4-buffer ring, depth-2 prefetch. 1 barrier/step.
// ---------------------------------------------------------------------------
__device__ __forceinline__ float log_add_exp(float a, float b) {
    float m = fmaxf(a, b);
    float d = fminf(a, b) - m;
    return m + log1pf(__expf(d));
}

__global__ __launch_bounds__(128) void k_scan(const int* __restrict__ num_frames,
                                              const int* __restrict__ labels,
                                              const int* __restrict__ num_labels,
                                              float* __restrict__ out) {
    extern __shared__ __align__(16) float tilebuf[];   // 4 * TILE_PAD floats
    __shared__ float beta_sh[2][68];
    __shared__ float anum[2][Un + 1];
    __shared__ int ctx[Un + 1];
    __shared__ float maxw[3];

    const int b = blockIdx.x;
    const int tid = threadIdx.x;
    const int lane = tid & 31;
    const int Tb = num_frames[b];     // in [64, 128]

    if (tid < Un + 1) {
        ctx[tid] = (tid == 0) ? 0 : labels[b * Un + tid - 1];
        anum[0][tid] = (tid == 0) ? 0.f : NEG_INF;
    }
    if (tid < 68) beta_sh[0][tid] = (tid == 0) ? 1.f : 0.f;

    const bool den_lo = (tid < 64);
    const bool den_hi = (tid == 127);
    float av = den_hi ? 1.f : 0.f;    // linear beta of own state (v+1 / 0)
    int esum = 0;

    const float* base = g_den + (size_t)(b * Tn) * TILE_PAD;
    const uint32_t tbase = smem_u32(tilebuf);

    // prologue: tiles 0 and 1
#pragma unroll
    for (int s = 0; s < 2; s++) {
        const float* src = base + (size_t)s * TILE_PAD;
        uint32_t dst = tbase + s * TILE_BYTES;
        for (int i = tid; i < TILE_PAD / 4; i += 128)
            cp_async16(dst + i * 16, src + i * 4);
        CP_COMMIT();
    }

    for (int t = 0; t < Tb; t++) {
        if (t + 2 < Tb) {
            const float* src = base + (size_t)(t + 2) * TILE_PAD;
            uint32_t dst = tbase + ((t + 2) & 3) * TILE_BYTES;
            for (int i = tid; i < TILE_PAD / 4; i += 128)
                cp_async16(dst + i * 16, src + i * 4);
        }
        CP_COMMIT();
        CP_WAIT2();                 // tile t's group complete (<=2 pending)
        __syncthreads();            // tile t visible to all; beta buffer swap

        const float* Tt = tilebuf + (t & 3) * TILE_PAD;
        const int R = t & 1;
        const float* bsh = beta_sh[R];

        float nv = 0.f;
        if (den_lo) {
            const int v = tid;
            const float* rp = Tt + (v + 1) * CSTRIDE;
            float s0 = 0.f, s1 = 0.f, s2 = 0.f, s3 = 0.f;
#pragma unroll 8
            for (int c = 0; c < 64; c += 4) {
                s0 += bsh[c]     * rp[c];
                s1 += bsh[c + 1] * rp[c + 1];
                s2 += bsh[c + 2] * rp[c + 2];
                s3 += bsh[c + 3] * rp[c + 3];
            }
            float mv = (s0 + s1) + (s2 + s3) + bsh[64] * rp[64];
            nv = fmaf(av, Tt[v + 1], mv);      // stay: beta * exp(blank[v+1])
        } else if (den_hi) {
            nv = av * Tt[0];
        } else if (tid <= 64 + Un) {
            const int j = tid - 64;
            float a1 = anum[R][j] + __logf(Tt[ctx[j]]);
            float nn;
            if (j > 0) {
                float sh = anum[R][j - 1] + __logf(Tt[ctx[j] * CSTRIDE + ctx[j - 1]]);
                nn = log_add_exp(a1, sh);
            } else {
                nn = a1;
            }
            anum[1 - R][j] = nn;
        }

        // renorm every 4 steps (uniform branch; extra barrier only here)
        if ((t & 3) == 3) {
            if (den_lo) {
                float m = nv;
#pragma unroll
                for (int o = 16; o; o >>= 1) m = fmaxf(m, __shfl_xor_sync(0xffffffffu, m, o));
                if (lane == 0) maxw[tid >> 5] = m;
            }
            if (den_hi) maxw[2] = nv;
            __syncthreads();
            float gm = fmaxf(fmaxf(maxw[0], maxw[1]), maxw[2]);
            int e = ilogbf(gm);
            float sc = __int_as_float((uint32_t)(127 - e) << 23);  // 2^-e, exact
            if (den_lo || den_hi) { nv *= sc; esum += e; }
        }

        if (den_lo) { beta_sh[1 - R][tid + 1] = nv; av = nv; }
        else if (den_hi) { beta_sh[1 - R][0] = nv; av = nv; }
    }
    __syncthreads();

    if (tid == 0) {
        const float* bf = beta_sh[Tb & 1];
        float s = 0.f;
        for (int c = 0; c < Cn; c++) s += bf[c];
        float den = (float)((double)esum * 0.6931471805599453) + __logf(s);
        float num = anum[Tb & 1][num_labels[b]];
        out[b] = den - num;
    }
}

// ---------------------------------------------------------------------------
extern "C" void kernel_launch(void* const* d_in, const int* in_sizes, int n_in,
                              void* d_out, int out_size) {
    const float* frames = (const float*)d_in[0];   // (8,128,512)
    const float* Wf     = (const float*)d_in[1];   // (512,512)
    const float* ce     = (const float*)d_in[2];   // (65,512)
    const float* Wo     = (const float*)d_in[3];   // (512,65)
    const int* nf       = (const int*)d_in[4];     // (8,)
    const int* labels   = (const int*)d_in[5];     // (8,32)
    const int* nl       = (const int*)d_in[6];     // (8,)
    float* out = (float*)d_out;                    // (8,)

    cudaFuncSetAttribute(k_logits, cudaFuncAttributeMaxDynamicSharedMemorySize, DYN_SMEM);
    cudaFuncSetAttribute(k_scan, cudaFuncAttributeMaxDynamicSharedMemorySize, SCAN_SMEM);

    k_prep<<<4, 256>>>(Wo);
    k_proj<<<dim3(Hn / 32, (Bn * Tn) / 64), 128>>>(frames, Wf);
    k_logits<<<NB_LOGITS, 128, DYN_SMEM>>>(ce);
    k_scan<<<Bn, 128, SCAN_SMEM>>>(nf, labels, nl, out);
}

// round 7
// speedup vs baseline: 2.3893x; 1.1627x over previous
#include <cuda_runtime.h>
#include <cuda_bf16.h>
#include <math.h>
#include <stdint.h>

#define NEG_INF (-1e30f)

// Problem constants
#define Bn 8
#define Tn 128
#define Dn 512
#define Hn 512
#define Vn 64
#define Un 32
#define Cn 65          // V + 1
#define CSTRIDE 66     // even row stride -> conflict-free float2 LDS in scan
#define TILE_PAD 4352  // 34*128 floats per (b,t) tile (>= 65*66=4290), 16B-mult
#define TILE_BYTES (TILE_PAD * 4)   // 17408
#define MROWS (Bn * Tn * Cn)        // 66560 = 520 * 128
#define NB_LOGITS (MROWS / 128)     // 520

// SMEM tile geometry for k_logits (strides in bf16 elements)
#define ASTRIDE 520                 // 128 rows  x 512 k  (pad 8 -> conflict-free frags)
#define BSTRIDE 520                 // 72  rows  x 512 k
#define A_ELEMS (128 * ASTRIDE)     // 133120 B
#define B_ELEMS (72 * BSTRIDE)      //  74880 B
#define DYN_SMEM ((A_ELEMS + B_ELEMS) * 2)   // 208000 B
#define DSTRIDE 132                 // fp32 stage stride (conflict-free)

#define SCAN_SMEM (4 * TILE_BYTES)  // 69632 B, 4-deep cp.async ring

// Scratch (__device__ globals; zero-initialized, 16B-aligned for vector casts)
__device__ __align__(16) float g_proj[Bn * Tn * Hn];             // 2 MB
__device__ __align__(16) float g_den[Bn * Tn * TILE_PAD];        // [bt][k*66 + c] = exp(logit)
__device__ __align__(16) __nv_bfloat16 g_WoutT[72 * 512];        // WoutT[n][k] = Wout[k][n], bf16

// ---------------------------------------------------------------------------
__device__ __forceinline__ float tanh_fast(float x) {
    float y; asm("tanh.approx.f32 %0, %1;" : "=f"(y) : "f"(x)); return y;
}
__device__ __forceinline__ uint32_t smem_u32(const void* p) {
    uint32_t a;
    asm("{ .reg .u64 t; cvta.to.shared.u64 t, %1; cvt.u32.u64 %0, t; }" : "=r"(a) : "l"(p));
    return a;
}
__device__ __forceinline__ void cp_async16(uint32_t saddr, const void* g) {
    asm volatile("cp.async.cg.shared.global [%0], [%1], 16;" :: "r"(saddr), "l"(g));
}
#define CP_COMMIT() asm volatile("cp.async.commit_group;" ::: "memory")
#define CP_WAIT3()  asm volatile("cp.async.wait_group 3;" ::: "memory")
#define CP_WAIT0()  asm volatile("cp.async.wait_group 0;" ::: "memory")

__device__ __forceinline__ void mma16816(float* c, const uint32_t* a, const uint32_t* b) {
    asm volatile(
        "mma.sync.aligned.m16n8k16.row.col.f32.bf16.bf16.f32 "
        "{%0,%1,%2,%3}, {%4,%5,%6,%7}, {%8,%9}, {%0,%1,%2,%3};"
        : "+f"(c[0]), "+f"(c[1]), "+f"(c[2]), "+f"(c[3])
        : "r"(a[0]), "r"(a[1]), "r"(a[2]), "r"(a[3]), "r"(b[0]), "r"(b[1]));
}
__device__ __forceinline__ uint32_t to_tf32(float f) {
    uint32_t u; asm("cvt.rna.tf32.f32 %0, %1;" : "=r"(u) : "f"(f)); return u;
}
__device__ __forceinline__ void mma_tf32(float* c, const uint32_t* a, const uint32_t* b) {
    asm volatile(
        "mma.sync.aligned.m16n8k8.row.col.f32.tf32.tf32.f32 "
        "{%0,%1,%2,%3}, {%4,%5,%6,%7}, {%8,%9}, {%0,%1,%2,%3};"
        : "+f"(c[0]), "+f"(c[1]), "+f"(c[2]), "+f"(c[3])
        : "r"(a[0]), "r"(a[1]), "r"(a[2]), "r"(a[3]), "r"(b[0]), "r"(b[1]));
}

// ---------------------------------------------------------------------------
// Kernel 0: transpose + bf16-convert Wout -> g_WoutT[n][k]  (rows n>=65 zero)
// ---------------------------------------------------------------------------
__global__ void k_prep(const float* __restrict__ Wo) {
    const int tid = threadIdx.x + blockIdx.x * blockDim.x;
    for (int e = tid; e < 72 * 512; e += blockDim.x * gridDim.x) {
        int n = e >> 9;
        int k = e & 511;
        float v = (n < Cn) ? Wo[k * Cn + n] : 0.f;
        g_WoutT[e] = __float2bfloat16(v);
    }
}

// ---------------------------------------------------------------------------
// Kernel 1: proj = frames @ W_frame via tf32 mma.sync (m16n8k8).
// BM=64, BN=32, 128 threads (4 warps, 2x2), K-chunk 32, cp.async double buffer.
// 256 blocks.
// ---------------------------------------------------------------------------
#define PAS 36   // fp32 smem stride (32+4)

__global__ __launch_bounds__(128) void k_proj(const float* __restrict__ A,
                                              const float* __restrict__ Bm) {
    __shared__ __align__(16) float As2[2][64 * PAS];
    __shared__ __align__(16) float Bs2[2][32 * PAS];

    const int tid = threadIdx.x;
    const int wid = tid >> 5;
    const int lane = tid & 31;
    const int gq = lane >> 2;
    const int tg = lane & 3;
    const int bm = blockIdx.y * 64;
    const int bn = blockIdx.x * 32;
    const int wm = (wid >> 1) * 32;
    const int wn = (wid & 1) * 16;

    const uint32_t asb[2] = { smem_u32(As2[0]), smem_u32(As2[1]) };
    const uint32_t bsb[2] = { smem_u32(Bs2[0]), smem_u32(Bs2[1]) };

    auto issue = [&](int ch, int buf) {
        const int kc = ch * 32;
#pragma unroll
        for (int l = 0; l < 4; l++) {
            int o = tid + l * 128;            // 512 16B ops for A
            int row = o >> 3, seg = o & 7;
            cp_async16(asb[buf] + (row * PAS + seg * 4) * 4,
                       A + (size_t)(bm + row) * Dn + kc + seg * 4);
        }
#pragma unroll
        for (int l = 0; l < 2; l++) {
            int o = tid + l * 128;            // 256 16B ops for B
            int kr = o >> 3, seg = o & 7;
            cp_async16(bsb[buf] + (kr * PAS + seg * 4) * 4,
                       Bm + (size_t)(kc + kr) * Hn + bn + seg * 4);
        }
        CP_COMMIT();
    };

    float acc[2][2][4];
#pragma unroll
    for (int mt = 0; mt < 2; mt++)
#pragma unroll
        for (int nt = 0; nt < 2; nt++)
#pragma unroll
            for (int i = 0; i < 4; i++) acc[mt][nt][i] = 0.f;

    issue(0, 0);
    CP_WAIT0();
    __syncthreads();

    for (int ch = 0; ch < 16; ch++) {
        const int buf = ch & 1;
        if (ch + 1 < 16) issue(ch + 1, 1 - buf);

        const float* As = As2[buf];
        const float* Bs = Bs2[buf];
#pragma unroll
        for (int ks = 0; ks < 4; ks++) {
            const int k0 = ks * 8;
            uint32_t bf[2][2];
#pragma unroll
            for (int nt = 0; nt < 2; nt++) {
                int cb = wn + nt * 8 + gq;
                bf[nt][0] = to_tf32(Bs[(k0 + tg) * PAS + cb]);
                bf[nt][1] = to_tf32(Bs[(k0 + tg + 4) * PAS + cb]);
            }
#pragma unroll
            for (int mt = 0; mt < 2; mt++) {
                int rm = wm + mt * 16 + gq;
                uint32_t af[4];
                af[0] = to_tf32(As[rm * PAS + k0 + tg]);
                af[1] = to_tf32(As[(rm + 8) * PAS + k0 + tg]);
                af[2] = to_tf32(As[rm * PAS + k0 + tg + 4]);
                af[3] = to_tf32(As[(rm + 8) * PAS + k0 + tg + 4]);
#pragma unroll
                for (int nt = 0; nt < 2; nt++) mma_tf32(acc[mt][nt], af, bf[nt]);
            }
        }
        CP_WAIT0();
        __syncthreads();
    }

#pragma unroll
    for (int mt = 0; mt < 2; mt++) {
        int row = bm + wm + mt * 16 + gq;
#pragma unroll
        for (int nt = 0; nt < 2; nt++) {
            int col = bn + wn + nt * 8 + tg * 2;
            *reinterpret_cast<float2*>(&g_proj[(size_t)row * Hn + col]) =
                make_float2(acc[mt][nt][0], acc[mt][nt][1]);
            *reinterpret_cast<float2*>(&g_proj[(size_t)(row + 8) * Hn + col]) =
                make_float2(acc[mt][nt][2], acc[mt][nt][3]);
        }
    }
}

// ---------------------------------------------------------------------------
// Kernel 2: logits via mma.sync bf16 (m16n8k16), 256 threads (8 warps).
// Block = 128 flattened (bt,c) rows, N=72 (65 valid), K=512 fully in SMEM.
// Epilogue stages D in SMEM, stores EXP of all logits transposed into
// g_den[bt][k*66 + c] (k=0 is blank).
// ---------------------------------------------------------------------------
__global__ __launch_bounds__(256) void k_logits(const float* __restrict__ ce) {
    extern __shared__ __align__(16) __nv_bfloat16 dynsmem[];
    __nv_bfloat16* Asm = dynsmem;              // [128][ASTRIDE]
    __nv_bfloat16* Bsm = dynsmem + A_ELEMS;    // [72][BSTRIDE]
    __shared__ __align__(16) float p[3 * 512];
    __shared__ int btc[128];                    // r -> bt*TILE_PAD + c

    const int tid = threadIdx.x;
    const int wid = tid >> 5;
    const int lane = tid & 31;
    const int gq = lane >> 2;
    const int tg = lane & 3;
    const int g0 = blockIdx.x * 128;
    const int bt0 = g0 / 65;

    // proj rows this block touches (<=3 bts)
    for (int i = tid; i < 3 * 512; i += 256) {
        int bt = bt0 + (i >> 9);
        p[i] = (bt < Bn * Tn) ? g_proj[(size_t)bt * Hn + (i & 511)] : 0.f;
    }
    // copy pre-transposed bf16 B tile (src stride 512 -> dst stride 520)
    for (int e = tid; e < 72 * 64; e += 256) {
        int n = e >> 6, kq = e & 63;
        *reinterpret_cast<uint4*>(&Bsm[n * BSTRIDE + kq * 8]) =
            *reinterpret_cast<const uint4*>(&g_WoutT[n * 512 + kq * 8]);
    }
    if (tid < 128) {
        int bt = (g0 + tid) / 65;
        btc[tid] = bt * TILE_PAD + (g0 + tid - bt * 65);
    }
    __syncthreads();

    // A tile: row-walk, division-free. 256 threads = 128 col-groups x 2 row-halves.
    {
        const int half = tid >> 7;           // 0/1 -> rows [0,64) / [64,128)
        const int col = (tid & 127) * 4;
        int g = g0 + half * 64;
        int bt = g / 65;
        int c = g - bt * 65;
#pragma unroll 4
        for (int rr = 0; rr < 64; rr++) {
            int r = half * 64 + rr;
            int pb = bt - bt0;
            float4 pe = *reinterpret_cast<const float4*>(&p[pb * 512 + col]);
            float4 cv = *reinterpret_cast<const float4*>(&ce[(size_t)c * Hn + col]);
            __nv_bfloat162 b0 = __floats2bfloat162_rn(tanh_fast(pe.x + cv.x),
                                                      tanh_fast(pe.y + cv.y));
            __nv_bfloat162 b1 = __floats2bfloat162_rn(tanh_fast(pe.z + cv.z),
                                                      tanh_fast(pe.w + cv.w));
            uint2 pk = make_uint2(*reinterpret_cast<uint32_t*>(&b0),
                                  *reinterpret_cast<uint32_t*>(&b1));
            *reinterpret_cast<uint2*>(&Asm[r * ASTRIDE + col]) = pk;
            if (++c == 65) { c = 0; ++bt; }
        }
    }
    __syncthreads();

    // Main loop: 8 warps, each 16 rows x 9 n-tiles
    float acc[9][4];
#pragma unroll
    for (int nt = 0; nt < 9; nt++)
#pragma unroll
        for (int i = 0; i < 4; i++) acc[nt][i] = 0.f;

    const int wbase = wid * 16;
#pragma unroll 2
    for (int kk = 0; kk < 32; kk++) {
        const int k0 = kk * 16;
        uint32_t bf[9][2];
#pragma unroll
        for (int nt = 0; nt < 9; nt++) {
            int n = nt * 8 + gq;
            bf[nt][0] = *reinterpret_cast<const uint32_t*>(&Bsm[n * BSTRIDE + k0 + tg * 2]);
            bf[nt][1] = *reinterpret_cast<const uint32_t*>(&Bsm[n * BSTRIDE + k0 + 8 + tg * 2]);
        }
        const int r0 = wbase + gq;
        uint32_t af[4];
        af[0] = *reinterpret_cast<const uint32_t*>(&Asm[r0 * ASTRIDE + k0 + tg * 2]);
        af[1] = *reinterpret_cast<const uint32_t*>(&Asm[(r0 + 8) * ASTRIDE + k0 + tg * 2]);
        af[2] = *reinterpret_cast<const uint32_t*>(&Asm[r0 * ASTRIDE + k0 + 8 + tg * 2]);
        af[3] = *reinterpret_cast<const uint32_t*>(&Asm[(r0 + 8) * ASTRIDE + k0 + 8 + tg * 2]);
#pragma unroll
        for (int nt = 0; nt < 9; nt++) mma16816(acc[nt], af, bf[nt]);
    }
    __syncthreads();   // done reading Asm/Bsm; reuse as stage

    // Stage D into SMEM: d_sm[col][row], stride DSTRIDE (conflict-free)
    float* d_sm = reinterpret_cast<float*>(dynsmem);   // 72*132 floats
    {
        const int r0 = wbase + gq;
#pragma unroll
        for (int nt = 0; nt < 9; nt++) {
            const int col = nt * 8 + tg * 2;
            d_sm[col * DSTRIDE + r0]           = acc[nt][0];
            d_sm[(col + 1) * DSTRIDE + r0]     = acc[nt][1];
            d_sm[col * DSTRIDE + r0 + 8]       = acc[nt][2];
            d_sm[(col + 1) * DSTRIDE + r0 + 8] = acc[nt][3];
        }
    }
    __syncthreads();

    // Drain: exp() of every logit, coalesced across r
    for (int e = tid; e < Cn * 128; e += 256) {
        int k = e >> 7;
        int r = e & 127;
        g_den[(size_t)btc[r] + k * CSTRIDE] = __expf(d_sm[k * DSTRIDE + r]);
    }
}

// ---------------------------------------------------------------------------
// Kernel 3: scans, one block/batch, 128 threads. NO transcendentals in loop.
// Denominator (tid 0..63 state v+1, tid 127 state 0): linear beta, float2
//   matvec, power-of-2 global renorm every 4 steps.
// Numerator (tid 64..96): linear with PER-STATE (mantissa, exponent) pairs.
// Tiles streamed by cp.async, 4-buffer ring, prefetch distance 3.
// ---------------------------------------------------------------------------
__global__ __launch_bounds__(128) void k_scan(const int* __restrict__ num_frames,
                                              const int* __restrict__ labels,
                                              const int* __restrict__ num_labels,
                                              float* __restrict__ out) {
    extern __shared__ __align__(16) float tilebuf[];   // 4 * TILE_PAD floats
    __shared__ __align__(16) float beta_sh[2][68];
    __shared__ float nmant[2][Un + 1];
    __shared__ int nexp[2][Un + 1];
    __shared__ int ctx[Un + 1];
    __shared__ float maxw[3];

    const int b = blockIdx.x;
    const int tid = threadIdx.x;
    const int lane = tid & 31;
    const int Tb = num_frames[b];     // in [64, 128]

    if (tid < Un + 1) {
        ctx[tid] = (tid == 0) ? 0 : labels[b * Un + tid - 1];
        nmant[0][tid] = (tid == 0) ? 1.f : 0.f;
        nexp[0][tid] = 0;
    }
    if (tid < 68) { beta_sh[0][tid] = (tid == 0) ? 1.f : 0.f; beta_sh[1][tid] = 0.f; }

    const bool den_lo = (tid < 64);
    const bool den_hi = (tid == 127);
    const bool num_th = (tid >= 64 && tid <= 64 + Un);
    float av = den_hi ? 1.f : 0.f;    // linear beta of own state (v+1 / 0)
    int esum = 0;

    const float* base = g_den + (size_t)(b * Tn) * TILE_PAD;
    const uint32_t tbase = smem_u32(tilebuf);

    // prologue: tiles 0..2 (3 groups)
#pragma unroll
    for (int s = 0; s < 3; s++) {
        const float* src = base + (size_t)s * TILE_PAD;
        uint32_t dst = tbase + s * TILE_BYTES;
        for (int i = tid; i < TILE_PAD / 4; i += 128)
            cp_async16(dst + i * 16, src + i * 4);
        CP_COMMIT();
    }

    for (int t = 0; t < Tb; t++) {
        if (t + 3 < Tb) {
            const float* src = base + (size_t)(t + 3) * TILE_PAD;
            uint32_t dst = tbase + ((t + 3) & 3) * TILE_BYTES;
            for (int i = tid; i < TILE_PAD / 4; i += 128)
                cp_async16(dst + i * 16, src + i * 4);
        }
        CP_COMMIT();
        CP_WAIT3();                 // tile t complete (<=3 groups pending)
        __syncthreads();            // tile t + state buffers visible

        const float* Tt = tilebuf + (t & 3) * TILE_PAD;
        const int R = t & 1;
        const float* bsh = beta_sh[R];

        float nv = 0.f;
        if (den_lo) {
            const int v = tid;
            const float2* r2 = reinterpret_cast<const float2*>(Tt + (v + 1) * CSTRIDE);
            const float2* e2 = reinterpret_cast<const float2*>(bsh);
            float s0 = 0.f, s1 = 0.f, s2 = 0.f, s3 = 0.f;
#pragma unroll 8
            for (int c2 = 0; c2 < 32; c2 += 2) {
                float2 a0 = r2[c2],     b0 = e2[c2];
                float2 a1 = r2[c2 + 1], b1 = e2[c2 + 1];
                s0 += a0.x * b0.x; s1 += a0.y * b0.y;
                s2 += a1.x * b1.x; s3 += a1.y * b1.y;
            }
            float mv = (s0 + s1) + (s2 + s3) + r2[32].x * bsh[64];
            nv = fmaf(av, Tt[v + 1], mv);      // stay: beta * exp(blank[v+1])
        } else if (den_hi) {
            nv = av * Tt[0];
        } else if (num_th) {
            const int j = tid - 64;
            float mj = nmant[R][j];
            int ej = nexp[R][j];
            float own = mj * Tt[ctx[j]];       // m_j * exp(blank at ctx)
            float nn; int basee;
            if (j > 0) {
                float mp = nmant[R][j - 1];
                int ep = nexp[R][j - 1];
                float oth = mp * Tt[ctx[j] * CSTRIDE + ctx[j - 1]];
                basee = (ej > ep) ? ej : ep;
                nn = ldexpf(own, ej - basee) + ldexpf(oth, ep - basee);
            } else {
                basee = ej;
                nn = own;
            }
            float mo; int eo;
            if (nn > 0.f) {
                int s = ilogbf(nn);
                mo = ldexpf(nn, -s);
                eo = basee + s;
            } else { mo = 0.f; eo = basee; }
            nmant[1 - R][j] = mo;
            nexp[1 - R][j] = eo;
        }

        // denominator renorm every 4 steps
        if ((t & 3) == 3) {
            if (den_lo) {
                float m = nv;
#pragma unroll
                for (int o = 16; o; o >>= 1) m = fmaxf(m, __shfl_xor_sync(0xffffffffu, m, o));
                if (lane == 0) maxw[tid >> 5] = m;
            }
            if (den_hi) maxw[2] = nv;
            __syncthreads();
            float gm = fmaxf(fmaxf(maxw[0], maxw[1]), maxw[2]);
            int e = ilogbf(gm);
            float sc = __int_as_float((uint32_t)(127 - e) << 23);  // 2^-e, exact
            if (den_lo || den_hi) { nv *= sc; esum += e; }
        }

        if (den_lo) { beta_sh[1 - R][tid + 1] = nv; av = nv; }
        else if (den_hi) { beta_sh[1 - R][0] = nv; av = nv; }
    }
    __syncthreads();

    if (tid == 0) {
        const float* bf = beta_sh[Tb & 1];
        float s = 0.f;
        for (int c = 0; c < Cn; c++) s += bf[c];
        float den = (float)((double)esum * 0.6931471805599453) + __logf(s);
        int nl = num_labels[b];
        float num = __logf(nmant[Tb & 1][nl])
                  + (float)((double)nexp[Tb & 1][nl] * 0.6931471805599453);
        out[b] = den - num;
    }
}

// ---------------------------------------------------------------------------
extern "C" void kernel_launch(void* const* d_in, const int* in_sizes, int n_in,
                              void* d_out, int out_size) {
    const float* frames = (const float*)d_in[0];   // (8,128,512)
    const float* Wf     = (const float*)d_in[1];   // (512,512)
    const float* ce     = (const float*)d_in[2];   // (65,512)
    const float* Wo     = (const float*)d_in[3];   // (512,65)
    const int* nf       = (const int*)d_in[4];     // (8,)
    const int* labels   = (const int*)d_in[5];     // (8,32)
    const int* nl       = (const int*)d_in[6];     // (8,)
    float* out = (float*)d_out;                    // (8,)

    cudaFuncSetAttribute(k_logits, cudaFuncAttributeMaxDynamicSharedMemorySize, DYN_SMEM);
    cudaFuncSetAttribute(k_scan, cudaFuncAttributeMaxDynamicSharedMemorySize, SCAN_SMEM);

    k_prep<<<4, 256>>>(Wo);
    k_proj<<<dim3(Hn / 32, (Bn * Tn) / 64), 128>>>(frames, Wf);
    k_logits<<<NB_LOGITS, 256, DYN_SMEM>>>(ce);
    k_scan<<<Bn, 128, SCAN_SMEM>>>(nf, labels, nl, out);
}

// round 8
// speedup vs baseline: 2.5808x; 1.0802x over previous
#include <cuda_runtime.h>
#include <cuda_bf16.h>
#include <math.h>
#include <stdint.h>

#define NEG_INF (-1e30f)

// Problem constants
#define Bn 8
#define Tn 128
#define Dn 512
#define Hn 512
#define Vn 64
#define Un 32
#define Cn 65          // V + 1
#define CSTRIDE 67     // odd -> banks 3*(v+1) mod 32, conflict-free scalar LDS
#define TILE_PAD 4480  // 35*128 floats per (b,t) tile (>= 65*67=4355)
#define TILE_BYTES (TILE_PAD * 4)   // 17920
#define MROWS (Bn * Tn * Cn)        // 66560 = 520 * 128
#define NB_LOGITS (MROWS / 128)     // 520

// SMEM tile geometry for k_logits (strides in bf16 elements)
#define ASTRIDE 520
#define BSTRIDE 520
#define A_ELEMS (128 * ASTRIDE)
#define B_ELEMS (72 * BSTRIDE)
#define DYN_SMEM ((A_ELEMS + B_ELEMS) * 2)   // 208000 B
#define DSTRIDE 132

#define SCAN_SMEM (4 * TILE_BYTES)  // 71680 B ring
#define EMIN (-(1 << 28))
#define LN2F 0.69314718055994531f

// Scratch (__device__ globals; zero-initialized, 16B-aligned for vector casts)
__device__ __align__(16) float g_proj[Bn * Tn * Hn];
__device__ __align__(16) float g_den[Bn * Tn * TILE_PAD];        // [bt][k*67 + c] = exp(logit)
__device__ __align__(16) __nv_bfloat16 g_WoutT[72 * 512];

// ---------------------------------------------------------------------------
__device__ __forceinline__ float tanh_fast(float x) {
    float y; asm("tanh.approx.f32 %0, %1;" : "=f"(y) : "f"(x)); return y;
}
__device__ __forceinline__ uint32_t smem_u32(const void* p) {
    uint32_t a;
    asm("{ .reg .u64 t; cvta.to.shared.u64 t, %1; cvt.u32.u64 %0, t; }" : "=r"(a) : "l"(p));
    return a;
}
__device__ __forceinline__ void cp_async16(uint32_t saddr, const void* g) {
    asm volatile("cp.async.cg.shared.global [%0], [%1], 16;" :: "r"(saddr), "l"(g));
}
#define CP_COMMIT() asm volatile("cp.async.commit_group;" ::: "memory")
#define CP_WAIT0()  asm volatile("cp.async.wait_group 0;" ::: "memory")

#define MBAR_INIT(addr, cnt) \
    asm volatile("mbarrier.init.shared.b64 [%0], %1;" :: "r"(addr), "r"((uint32_t)(cnt)) : "memory")
#define MBAR_ARRIVE(addr) \
    asm volatile("mbarrier.arrive.shared.b64 _, [%0];" :: "r"(addr) : "memory")

__device__ __forceinline__ void mbar_wait(uint32_t addr, uint32_t phase) {
    asm volatile(
        "{\n\t.reg .pred P;\n\t"
        "LW_%=:\n\t"
        "mbarrier.try_wait.parity.acquire.cta.shared::cta.b64 P, [%0], %1, 0x989680;\n\t"
        "@P bra.uni LD_%=;\n\t"
        "bra.uni LW_%=;\n\t"
        "LD_%=:\n\t}"
        :: "r"(addr), "r"(phase) : "memory");
}

__device__ __forceinline__ void mma16816(float* c, const uint32_t* a, const uint32_t* b) {
    asm volatile(
        "mma.sync.aligned.m16n8k16.row.col.f32.bf16.bf16.f32 "
        "{%0,%1,%2,%3}, {%4,%5,%6,%7}, {%8,%9}, {%0,%1,%2,%3};"
        : "+f"(c[0]), "+f"(c[1]), "+f"(c[2]), "+f"(c[3])
        : "r"(a[0]), "r"(a[1]), "r"(a[2]), "r"(a[3]), "r"(b[0]), "r"(b[1]));
}
__device__ __forceinline__ uint32_t to_tf32(float f) {
    uint32_t u; asm("cvt.rna.tf32.f32 %0, %1;" : "=r"(u) : "f"(f)); return u;
}
__device__ __forceinline__ void mma_tf32(float* c, const uint32_t* a, const uint32_t* b) {
    asm volatile(
        "mma.sync.aligned.m16n8k8.row.col.f32.tf32.tf32.f32 "
        "{%0,%1,%2,%3}, {%4,%5,%6,%7}, {%8,%9}, {%0,%1,%2,%3};"
        : "+f"(c[0]), "+f"(c[1]), "+f"(c[2]), "+f"(c[3])
        : "r"(a[0]), "r"(a[1]), "r"(a[2]), "r"(a[3]), "r"(b[0]), "r"(b[1]));
}

// 2^d for d in [-127, 127], exact, branchless
__device__ __forceinline__ float exp2i(int d) {
    return __int_as_float((d + 127) << 23);
}
// (m,e) <- own*2^eo + oth*2^ep, with own,oth >= 0; m in [1,2) or 0.
__device__ __forceinline__ void accum2(float own, int eo, float oth, int ep,
                                       float& m, int& e) {
    int base = (eo > ep) ? eo : ep;
    int d0 = eo - base; d0 = (d0 < -127) ? -127 : d0;
    int d1 = ep - base; d1 = (d1 < -127) ? -127 : d1;
    float nn = own * exp2i(d0) + oth * exp2i(d1);
    if (nn > 0.f) {
        int bits = __float_as_int(nn);
        e = base + ((bits >> 23) & 0xFF) - 127;
        m = __int_as_float((bits & 0x007FFFFF) | 0x3F800000);
    } else {
        m = 0.f; e = EMIN;
    }
}

// ---------------------------------------------------------------------------
// Kernel 0: transpose + bf16-convert Wout -> g_WoutT[n][k]  (rows n>=65 zero)
// ---------------------------------------------------------------------------
__global__ void k_prep(const float* __restrict__ Wo) {
    const int tid = threadIdx.x + blockIdx.x * blockDim.x;
    for (int e = tid; e < 72 * 512; e += blockDim.x * gridDim.x) {
        int n = e >> 9;
        int k = e & 511;
        float v = (n < Cn) ? Wo[k * Cn + n] : 0.f;
        g_WoutT[e] = __float2bfloat16(v);
    }
}

// ---------------------------------------------------------------------------
// Kernel 1: proj = frames @ W_frame via tf32 mma.sync (m16n8k8).
// ---------------------------------------------------------------------------
#define PAS 36

__global__ __launch_bounds__(128) void k_proj(const float* __restrict__ A,
                                              const float* __restrict__ Bm) {
    __shared__ __align__(16) float As2[2][64 * PAS];
    __shared__ __align__(16) float Bs2[2][32 * PAS];

    const int tid = threadIdx.x;
    const int wid = tid >> 5;
    const int lane = tid & 31;
    const int gq = lane >> 2;
    const int tg = lane & 3;
    const int bm = blockIdx.y * 64;
    const int bn = blockIdx.x * 32;
    const int wm = (wid >> 1) * 32;
    const int wn = (wid & 1) * 16;

    const uint32_t asb[2] = { smem_u32(As2[0]), smem_u32(As2[1]) };
    const uint32_t bsb[2] = { smem_u32(Bs2[0]), smem_u32(Bs2[1]) };

    auto issue = [&](int ch, int buf) {
        const int kc = ch * 32;
#pragma unroll
        for (int l = 0; l < 4; l++) {
            int o = tid + l * 128;
            int row = o >> 3, seg = o & 7;
            cp_async16(asb[buf] + (row * PAS + seg * 4) * 4,
                       A + (size_t)(bm + row) * Dn + kc + seg * 4);
        }
#pragma unroll
        for (int l = 0; l < 2; l++) {
            int o = tid + l * 128;
            int kr = o >> 3, seg = o & 7;
            cp_async16(bsb[buf] + (kr * PAS + seg * 4) * 4,
                       Bm + (size_t)(kc + kr) * Hn + bn + seg * 4);
        }
        CP_COMMIT();
    };

    float acc[2][2][4];
#pragma unroll
    for (int mt = 0; mt < 2; mt++)
#pragma unroll
        for (int nt = 0; nt < 2; nt++)
#pragma unroll
            for (int i = 0; i < 4; i++) acc[mt][nt][i] = 0.f;

    issue(0, 0);
    CP_WAIT0();
    __syncthreads();

    for (int ch = 0; ch < 16; ch++) {
        const int buf = ch & 1;
        if (ch + 1 < 16) issue(ch + 1, 1 - buf);

        const float* As = As2[buf];
        const float* Bs = Bs2[buf];
#pragma unroll
        for (int ks = 0; ks < 4; ks++) {
            const int k0 = ks * 8;
            uint32_t bf[2][2];
#pragma unroll
            for (int nt = 0; nt < 2; nt++) {
                int cb = wn + nt * 8 + gq;
                bf[nt][0] = to_tf32(Bs[(k0 + tg) * PAS + cb]);
                bf[nt][1] = to_tf32(Bs[(k0 + tg + 4) * PAS + cb]);
            }
#pragma unroll
            for (int mt = 0; mt < 2; mt++) {
                int rm = wm + mt * 16 + gq;
                uint32_t af[4];
                af[0] = to_tf32(As[rm * PAS + k0 + tg]);
                af[1] = to_tf32(As[(rm + 8) * PAS + k0 + tg]);
                af[2] = to_tf32(As[rm * PAS + k0 + tg + 4]);
                af[3] = to_tf32(As[(rm + 8) * PAS + k0 + tg + 4]);
#pragma unroll
                for (int nt = 0; nt < 2; nt++) mma_tf32(acc[mt][nt], af, bf[nt]);
            }
        }
        CP_WAIT0();
        __syncthreads();
    }

#pragma unroll
    for (int mt = 0; mt < 2; mt++) {
        int row = bm + wm + mt * 16 + gq;
#pragma unroll
        for (int nt = 0; nt < 2; nt++) {
            int col = bn + wn + nt * 8 + tg * 2;
            *reinterpret_cast<float2*>(&g_proj[(size_t)row * Hn + col]) =
                make_float2(acc[mt][nt][0], acc[mt][nt][1]);
            *reinterpret_cast<float2*>(&g_proj[(size_t)(row + 8) * Hn + col]) =
                make_float2(acc[mt][nt][2], acc[mt][nt][3]);
        }
    }
}

// ---------------------------------------------------------------------------
// Kernel 2: logits via mma.sync bf16 (m16n8k16), 256 threads (8 warps).
// Stores EXP of all logits transposed into g_den[bt][k*67 + c].
// ---------------------------------------------------------------------------
__global__ __launch_bounds__(256) void k_logits(const float* __restrict__ ce) {
    extern __shared__ __align__(16) __nv_bfloat16 dynsmem[];
    __nv_bfloat16* Asm = dynsmem;
    __nv_bfloat16* Bsm = dynsmem + A_ELEMS;
    __shared__ __align__(16) float p[3 * 512];
    __shared__ int btc[128];

    const int tid = threadIdx.x;
    const int wid = tid >> 5;
    const int lane = tid & 31;
    const int gq = lane >> 2;
    const int tg = lane & 3;
    const int g0 = blockIdx.x * 128;
    const int bt0 = g0 / 65;

    for (int i = tid; i < 3 * 512; i += 256) {
        int bt = bt0 + (i >> 9);
        p[i] = (bt < Bn * Tn) ? g_proj[(size_t)bt * Hn + (i & 511)] : 0.f;
    }
    for (int e = tid; e < 72 * 64; e += 256) {
        int n = e >> 6, kq = e & 63;
        *reinterpret_cast<uint4*>(&Bsm[n * BSTRIDE + kq * 8]) =
            *reinterpret_cast<const uint4*>(&g_WoutT[n * 512 + kq * 8]);
    }
    if (tid < 128) {
        int bt = (g0 + tid) / 65;
        btc[tid] = bt * TILE_PAD + (g0 + tid - bt * 65);
    }
    __syncthreads();

    {
        const int half = tid >> 7;
        const int col = (tid & 127) * 4;
        int g = g0 + half * 64;
        int bt = g / 65;
        int c = g - bt * 65;
#pragma unroll 4
        for (int rr = 0; rr < 64; rr++) {
            int r = half * 64 + rr;
            int pb = bt - bt0;
            float4 pe = *reinterpret_cast<const float4*>(&p[pb * 512 + col]);
            float4 cv = *reinterpret_cast<const float4*>(&ce[(size_t)c * Hn + col]);
            __nv_bfloat162 b0 = __floats2bfloat162_rn(tanh_fast(pe.x + cv.x),
                                                      tanh_fast(pe.y + cv.y));
            __nv_bfloat162 b1 = __floats2bfloat162_rn(tanh_fast(pe.z + cv.z),
                                                      tanh_fast(pe.w + cv.w));
            uint2 pk = make_uint2(*reinterpret_cast<uint32_t*>(&b0),
                                  *reinterpret_cast<uint32_t*>(&b1));
            *reinterpret_cast<uint2*>(&Asm[r * ASTRIDE + col]) = pk;
            if (++c == 65) { c = 0; ++bt; }
        }
    }
    __syncthreads();

    float acc[9][4];
#pragma unroll
    for (int nt = 0; nt < 9; nt++)
#pragma unroll
        for (int i = 0; i < 4; i++) acc[nt][i] = 0.f;

    const int wbase = wid * 16;
#pragma unroll 2
    for (int kk = 0; kk < 32; kk++) {
        const int k0 = kk * 16;
        uint32_t bf[9][2];
#pragma unroll
        for (int nt = 0; nt < 9; nt++) {
            int n = nt * 8 + gq;
            bf[nt][0] = *reinterpret_cast<const uint32_t*>(&Bsm[n * BSTRIDE + k0 + tg * 2]);
            bf[nt][1] = *reinterpret_cast<const uint32_t*>(&Bsm[n * BSTRIDE + k0 + 8 + tg * 2]);
        }
        const int r0 = wbase + gq;
        uint32_t af[4];
        af[0] = *reinterpret_cast<const uint32_t*>(&Asm[r0 * ASTRIDE + k0 + tg * 2]);
        af[1] = *reinterpret_cast<const uint32_t*>(&Asm[(r0 + 8) * ASTRIDE + k0 + tg * 2]);
        af[2] = *reinterpret_cast<const uint32_t*>(&Asm[r0 * ASTRIDE + k0 + 8 + tg * 2]);
        af[3] = *reinterpret_cast<const uint32_t*>(&Asm[(r0 + 8) * ASTRIDE + k0 + 8 + tg * 2]);
#pragma unroll
        for (int nt = 0; nt < 9; nt++) mma16816(acc[nt], af, bf[nt]);
    }
    __syncthreads();

    float* d_sm = reinterpret_cast<float*>(dynsmem);
    {
        const int r0 = wbase + gq;
#pragma unroll
        for (int nt = 0; nt < 9; nt++) {
            const int col = nt * 8 + tg * 2;
            d_sm[col * DSTRIDE + r0]           = acc[nt][0];
            d_sm[(col + 1) * DSTRIDE + r0]     = acc[nt][1];
            d_sm[col * DSTRIDE + r0 + 8]       = acc[nt][2];
            d_sm[(col + 1) * DSTRIDE + r0 + 8] = acc[nt][3];
        }
    }
    __syncthreads();

    for (int e = tid; e < Cn * 128; e += 256) {
        int k = e >> 7;
        int r = e & 127;
        g_den[(size_t)btc[r] + k * CSTRIDE] = __expf(d_sm[k * DSTRIDE + r]);
    }
}

// ---------------------------------------------------------------------------
// Kernel 3: warp-specialized scan. 224 threads, one block per batch.
//  warps 0-1 : denominator (lane v -> state v+1; tid31 also state 0),
//              linear beta, renorm every 4 steps, bar.sync 1,64 only.
//  warp 2    : numerator, 33 states, shuffle-only exchange, per-state (m,e).
//  warps 3-6 : producers; warp w owns ring slot (w-3); cp.async + wait_group 0
//              + mbarrier full/empty handshake (depth-4 ring).
// ---------------------------------------------------------------------------
__global__ __launch_bounds__(224) void k_scan(const int* __restrict__ num_frames,
                                              const int* __restrict__ labels,
                                              const int* __restrict__ num_labels,
                                              float* __restrict__ out) {
    extern __shared__ __align__(16) float tilebuf[];   // 4 * TILE_PAD floats
    __shared__ __align__(16) float beta_sh[2][68];
    __shared__ float maxw[2];
    __shared__ float nm_fin[Un + 1];
    __shared__ int ne_fin[Un + 1];
    __shared__ __align__(8) unsigned long long mbars[8];   // full[0..3], empty[4..7]

    const int b = blockIdx.x;
    const int tid = threadIdx.x;
    const int wid = tid >> 5;
    const int lane = tid & 31;
    const int Tb = num_frames[b];          // in [64, 128]

    uint32_t mb_full[4], mb_empty[4];
#pragma unroll
    for (int s = 0; s < 4; s++) {
        mb_full[s] = smem_u32(&mbars[s]);
        mb_empty[s] = smem_u32(&mbars[4 + s]);
    }
    if (tid == 0) {
#pragma unroll
        for (int s = 0; s < 4; s++) {
            MBAR_INIT(mb_full[s], 32);     // 32 producer-thread arrivals
            MBAR_INIT(mb_empty[s], 3);     // 3 consumer-warp elected arrivals
        }
    }
    // denominator beta init (before the barrier)
    if (wid < 2) {
        beta_sh[0][wid * 32 + lane + 1] = 0.f;
        if (tid == 31) beta_sh[0][0] = 1.f;
    }
    __syncthreads();

    const float* base = g_den + (size_t)(b * Tn) * TILE_PAD;
    int esum = 0;   // only meaningful on den threads; tid0 uses it at the end

    if (wid >= 3) {
        // ---- producer warp: slot p = wid-3, tiles t = p, p+4, ...
        const int p = wid - 3;
        const uint32_t dst0 = smem_u32(tilebuf) + p * TILE_BYTES;
        int eph = 1;                                   // first empty-wait passes
        for (int t = p; t < Tb; t += 4) {
            mbar_wait(mb_empty[p], (uint32_t)eph);
            eph ^= 1;
            const float* src = base + (size_t)t * TILE_PAD;
#pragma unroll 5
            for (int i = lane; i < TILE_PAD / 4; i += 32)
                cp_async16(dst0 + i * 16, src + i * 4);
            CP_COMMIT();
            CP_WAIT0();
            MBAR_ARRIVE(mb_full[p]);
        }
    } else if (wid < 2) {
        // ---- denominator
        const int v = wid * 32 + lane;                 // state v+1
        const bool ex = (tid == 31);                   // also state 0
        const int rowoff = (v + 1) * CSTRIDE;
        float av = 0.f;
        float av0 = ex ? 1.f : 0.f;

        for (int t = 0; t < Tb; t++) {
            const int s = t & 3;
            mbar_wait(mb_full[s], (uint32_t)((t >> 2) & 1));
            const float* Tt = tilebuf + s * TILE_PAD;
            const float* bsh = beta_sh[t & 1];
            const float* rp = Tt + rowoff;

            float s0 = 0.f, s1 = 0.f, s2 = 0.f, s3 = 0.f;
#pragma unroll 8
            for (int c = 0; c < 64; c += 4) {
                s0 += bsh[c]     * rp[c];
                s1 += bsh[c + 1] * rp[c + 1];
                s2 += bsh[c + 2] * rp[c + 2];
                s3 += bsh[c + 3] * rp[c + 3];
            }
            float mv = (s0 + s1) + (s2 + s3) + bsh[64] * rp[64];
            float nv = fmaf(av, Tt[v + 1], mv);
            float nv0 = ex ? av0 * Tt[0] : 0.f;

            __syncwarp();
            if (lane == 0) MBAR_ARRIVE(mb_empty[s]);   // this warp done with tile

            if ((t & 3) == 3) {
                float mx = fmaxf(nv, nv0);
#pragma unroll
                for (int o = 16; o; o >>= 1)
                    mx = fmaxf(mx, __shfl_xor_sync(0xffffffffu, mx, o));
                if (lane == 0) maxw[wid] = mx;
                asm volatile("bar.sync 1, 64;" ::: "memory");
                float gm = fmaxf(maxw[0], maxw[1]);
                int eb = ((__float_as_int(gm) >> 23) & 0xFF) - 127;
                float sc = exp2i(-eb);
                nv *= sc; nv0 *= sc; esum += eb;
            }

            beta_sh[1 - (t & 1)][v + 1] = nv;
            if (ex) beta_sh[1 - (t & 1)][0] = nv0;
            av = nv; av0 = nv0;
            asm volatile("bar.sync 1, 64;" ::: "memory");
        }
    } else {
        // ---- numerator (warp 2): lane j = state j; lane 0 also state 32
        const int* lb = labels + b * Un;
        const int j = lane;
        const int cj = (j == 0) ? 0 : lb[j - 1];
        const int cm = (j >= 2) ? lb[j - 2] : 0;
        const int c32 = lb[31], c31 = lb[30];
        float m = (j == 0) ? 1.f : 0.f;
        int e = (j == 0) ? 0 : EMIN;
        float m2 = 0.f;
        int e2 = EMIN;

        for (int t = 0; t < Tb; t++) {
            const int s = t & 3;
            mbar_wait(mb_full[s], (uint32_t)((t >> 2) & 1));
            const float* Tt = tilebuf + s * TILE_PAD;

            float mp = __shfl_up_sync(0xffffffffu, m, 1);
            int epv = __shfl_up_sync(0xffffffffu, e, 1);
            float m31 = __shfl_sync(0xffffffffu, m, 31);
            int e31 = __shfl_sync(0xffffffffu, e, 31);

            float own = m * Tt[cj];
            float oth = (j > 0) ? mp * Tt[cj * CSTRIDE + cm] : 0.f;
            int epo = (j > 0) ? epv : EMIN;
            int eown = e;
            accum2(own, eown, oth, epo, m, e);

            if (j == 0) {
                float own2 = m2 * Tt[c32];
                float oth2 = m31 * Tt[c32 * CSTRIDE + c31];
                accum2(own2, e2, oth2, e31, m2, e2);
            }

            __syncwarp();
            if (lane == 0) MBAR_ARRIVE(mb_empty[s]);
        }
        nm_fin[j] = m;
        ne_fin[j] = e;
        if (j == 0) { nm_fin[32] = m2; ne_fin[32] = e2; }
    }

    __syncthreads();
    if (tid == 0) {
        const float* bf = beta_sh[Tb & 1];
        float ssum = 0.f;
        for (int c = 0; c < Cn; c++) ssum += bf[c];
        float den = (float)esum * LN2F + __logf(ssum);
        int nl = num_labels[b];
        float num = __logf(nm_fin[nl]) + (float)ne_fin[nl] * LN2F;
        out[b] = den - num;
    }
}

// ---------------------------------------------------------------------------
extern "C" void kernel_launch(void* const* d_in, const int* in_sizes, int n_in,
                              void* d_out, int out_size) {
    const float* frames = (const float*)d_in[0];   // (8,128,512)
    const float* Wf     = (const float*)d_in[1];   // (512,512)
    const float* ce     = (const float*)d_in[2];   // (65,512)
    const float* Wo     = (const float*)d_in[3];   // (512,65)
    const int* nf       = (const int*)d_in[4];     // (8,)
    const int* labels   = (const int*)d_in[5];     // (8,32)
    const int* nl       = (const int*)d_in[6];     // (8,)
    float* out = (float*)d_out;                    // (8,)

    cudaFuncSetAttribute(k_logits, cudaFuncAttributeMaxDynamicSharedMemorySize, DYN_SMEM);
    cudaFuncSetAttribute(k_scan, cudaFuncAttributeMaxDynamicSharedMemorySize, SCAN_SMEM);

    k_prep<<<4, 256>>>(Wo);
    k_proj<<<dim3(Hn / 32, (Bn * Tn) / 64), 128>>>(frames, Wf);
    k_logits<<<NB_LOGITS, 256, DYN_SMEM>>>(ce);
    k_scan<<<Bn, 224, SCAN_SMEM>>>(nf, labels, nl, out);
}